// round 15
// baseline (speedup 1.0000x reference)
#include <cuda_runtime.h>
#include <cuda_fp16.h>
#include <cstdint>

#define NVAR   9
#define NSCEN  4
#define IH0_W  137
#define INIT_W 160
#define MR     64      // batch rows per CTA
#define THREADS 512

// ---------------- device globals (built by setup_kernel each launch) --------
// B fragment image: [mat][kt 0..7][w 0..15][pr 0..1][lane 0..31][8 halfs]
//   pr=0 -> gates i,f ; pr=1 -> gates g,o  (two n=8 fragments per 16B)
//   fragment (n8 = gate*16 + w): n = gate*128 + w*8 + (lane>>2),
//   k = kt*16 + ((lane&3)<<1) + ((hf>>1)<<3) + (hf&1)
// mat: 0=W_hh0, 1=Wfold(=Wp*Wout), 2=W_ih1, 3=W_hh1 ; each [N=512, K=128]
__device__ __align__(16) __half g_Bpk[4 * 65536];
__device__ float g_P0[NSCEN * 512];   // se@Wih0_se + b_ih0 + b_hh0
__device__ float g_QI[NSCEN * 512];   // se@Winit_se + b_init
__device__ float g_bf[512];           // Wp @ b_out
__device__ float g_pre1[512];         // b_ih1 + b_hh1

__global__ void setup_kernel(const float* __restrict__ emb,
                             const float* __restrict__ W_init, const float* __restrict__ b_init,
                             const float* __restrict__ W_ih0,  const float* __restrict__ b_ih0,
                             const float* __restrict__ b_hh0,  const float* __restrict__ W_ih1,
                             const float* __restrict__ W_hh1,  const float* __restrict__ b_ih1,
                             const float* __restrict__ b_hh1,  const float* __restrict__ W_hh0,
                             const float* __restrict__ W_out,  const float* __restrict__ b_out) {
    int i = blockIdx.x * blockDim.x + threadIdx.x;
    if (i < 262144) {
        int mat = i >> 16, rem = i & 65535;
        int kt = rem >> 13;
        int r2 = rem & 8191;
        int w  = r2 >> 9;
        int r3 = r2 & 511;
        int pr = r3 >> 8;
        int r4 = r3 & 255;
        int lane = r4 >> 3, h = r4 & 7;
        int gate = pr * 2 + (h >> 2);
        int hf = h & 3;
        int k = kt * 16 + ((lane & 3) << 1) + ((hf >> 1) << 3) + (hf & 1);
        int n = gate * 128 + w * 8 + (lane >> 2);
        float v;
        if (mat == 0)      v = W_hh0[n * 128 + k];
        else if (mat == 1) { v = 0.f;
            for (int q = 0; q < NVAR; ++q) v += W_ih0[n * IH0_W + q] * W_out[q * 128 + k]; }
        else if (mat == 2) v = W_ih1[n * 128 + k];
        else               v = W_hh1[n * 128 + k];
        g_Bpk[i] = __float2half_rn(v);
    } else if (i < 262144 + 2048) {
        int j = i - 262144; int s = j >> 9, col = j & 511;
        float a = b_ih0[col] + b_hh0[col];
        const float* e = emb + s * 128; const float* wr = W_ih0 + col * IH0_W + NVAR;
        for (int k = 0; k < 128; ++k) a += e[k] * wr[k];
        g_P0[j] = a;
    } else if (i < 262144 + 4096) {
        int j = i - 262144 - 2048; int s = j >> 9, col = j & 511;
        float a = b_init[col];
        const float* e = emb + s * 128; const float* wr = W_init + col * INIT_W + 32;
        for (int k = 0; k < 128; ++k) a += e[k] * wr[k];
        g_QI[j] = a;
    } else if (i < 262144 + 4608) {
        int col = i - 262144 - 4096;
        float a = 0.f;
        for (int q = 0; q < NVAR; ++q) a += W_ih0[col * IH0_W + q] * b_out[q];
        g_bf[col] = a;
    } else if (i < 262144 + 5120) {
        int col = i - 262144 - 4608;
        g_pre1[col] = b_ih1[col] + b_hh1[col];
    }
}

// ---------------- SMEM byte offsets ----------------
#define O_H0    0          // 64 x 136 half (row stride 272B)
#define O_H1    17408
#define O_H1F   34816      // 64 x 132 float (stride 528B)
#define O_P0    68608      // 4 x 520 float
#define O_BF    76928      // 512 float
#define O_PRE1  78976      // 512 float
#define O_WOUT  81024      // 9 x 128 float
#define O_BOUT  85632      // 16 float
#define O_SCEN  85696      // 64 int
#define O_FLAG  85952
#define SMEM_SZ 86016

static __device__ __forceinline__ uint32_t smem_u32(const void* p) {
    uint32_t a;
    asm("{ .reg .u64 t; cvta.to.shared.u64 t, %1; cvt.u32.u64 %0, t; }" : "=r"(a) : "l"(p));
    return a;
}
static __device__ __forceinline__ void ldmat4(uint32_t* r, uint32_t addr) {
    asm volatile("ldmatrix.sync.aligned.m8n8.x4.shared.b16 {%0,%1,%2,%3}, [%4];"
        : "=r"(r[0]), "=r"(r[1]), "=r"(r[2]), "=r"(r[3]) : "r"(addr));
}
static __device__ __forceinline__ void mma16816(float* d, const uint32_t* a,
                                                uint32_t b0, uint32_t b1) {
    asm volatile("mma.sync.aligned.m16n8k16.row.col.f32.f16.f16.f32 "
        "{%0,%1,%2,%3}, {%4,%5,%6,%7}, {%8,%9}, {%0,%1,%2,%3};"
        : "+f"(d[0]), "+f"(d[1]), "+f"(d[2]), "+f"(d[3])
        : "r"(a[0]), "r"(a[1]), "r"(a[2]), "r"(a[3]), "r"(b0), "r"(b1));
}
static __device__ __forceinline__ float sigf(float x) {
    return __fdividef(1.0f, 1.0f + __expf(-x));
}
static __device__ __forceinline__ float tanhf_(float x) {
    return __fdividef(2.0f, 1.0f + __expf(-2.0f * x)) - 1.0f;
}

// one K=128 gemm accumulation: d[rt][gate][j] += A(h at hoff) @ B(mat)^T
static __device__ __forceinline__ void do_gemm(float d[4][4][4], const char* smbase,
                                               int hoff, int mat, int w, int lane) {
    uint32_t hb = smem_u32(smbase + hoff) + (lane & 15) * 272 + ((lane >> 4) << 4);
    const char* bp = (const char*)g_Bpk + (size_t)mat * 131072 + w * 1024 + lane * 16;
#pragma unroll
    for (int kt = 0; kt < 8; ++kt) {
        uint4 b01 = *(const uint4*)(bp + kt * 16384);
        uint4 b23 = *(const uint4*)(bp + kt * 16384 + 512);
#pragma unroll
        for (int rt = 0; rt < 4; ++rt) {
            uint32_t a[4];
            ldmat4(a, hb + rt * (16 * 272) + kt * 32);
            mma16816(d[rt][0], a, b01.x, b01.y);
            mma16816(d[rt][1], a, b01.z, b01.w);
            mma16816(d[rt][2], a, b23.x, b23.y);
            mma16816(d[rt][3], a, b23.z, b23.w);
        }
    }
}

__global__ void __launch_bounds__(THREADS, 1)
lstm_mma(const float* __restrict__ z, const int* __restrict__ scen_raw,
         const float* __restrict__ W_init, const float* __restrict__ W_out,
         const float* __restrict__ b_out, float* __restrict__ outp, int T) {
    extern __shared__ char sm[];
    float* shP0   = (float*)(sm + O_P0);
    float* shBF   = (float*)(sm + O_BF);
    float* shPre1 = (float*)(sm + O_PRE1);
    float* shWout = (float*)(sm + O_WOUT);
    float* shBout = (float*)(sm + O_BOUT);
    int*   shScen = (int*)(sm + O_SCEN);
    int*   shFlag = (int*)(sm + O_FLAG);

    const int tid = threadIdx.x;
    const int lane = tid & 31, w = tid >> 5;       // w = 0..15
    const int m0 = blockIdx.x * MR;

    if (tid == 0) *shFlag = 1;
    __syncthreads();
    {
        const unsigned* su = (const unsigned*)scen_raw;
        for (int k = tid; k < 512; k += THREADS)
            if (su[2 * k + 1] != 0u) *shFlag = 0;
    }
    __syncthreads();
    const int is64 = *shFlag;

    // tables
    for (int i = tid; i < NSCEN * 512; i += THREADS)
        shP0[(i >> 9) * 520 + (i & 511)] = g_P0[i];
    for (int i = tid; i < 512; i += THREADS) { shBF[i] = g_bf[i]; shPre1[i] = g_pre1[i]; }
    for (int i = tid; i < NVAR * 128; i += THREADS) shWout[i] = W_out[i];
    if (tid < NVAR) shBout[tid] = b_out[tid];
    for (int m = tid; m < MR; m += THREADS)
        shScen[m] = is64 ? scen_raw[2 * (m0 + m)] : scen_raw[m0 + m];
    __syncthreads();

    // thread's (row, unit) ownership: row = rt*16 + (lane>>2) + ((j>>1)<<3),
    // unit = w*8 + ((lane&3)<<1) + (j&1); gates via d[rt][g][j]
    float c0r[16], c1r[16];

    // ---- phase 1: h_init (z @ Winit_z^T + QI[scen]); c in regs, h fp16 ----
#pragma unroll
    for (int rt = 0; rt < 4; ++rt)
#pragma unroll
        for (int j = 0; j < 4; ++j) {
            int row = rt * 16 + (lane >> 2) + ((j >> 1) << 3);
            int u   = w * 8 + ((lane & 3) << 1) + (j & 1);
            int s = shScen[row];
            float v[4];
#pragma unroll
            for (int slot = 0; slot < 4; ++slot) {
                int jd = slot * 128 + u;
                float a = g_QI[s * 512 + jd];
                const float* zr = z + (size_t)(m0 + row) * 32;
                const float* wr = W_init + (size_t)jd * INIT_W;
                for (int k = 0; k < 32; ++k) a += zr[k] * wr[k];
                v[slot] = a;
            }
            int ci = rt * 4 + j;
            *(__half*)(sm + O_H0 + row * 272 + u * 2) = __float2half_rn(v[0]);
            c0r[ci] = v[1];
            *(__half*)(sm + O_H1 + row * 272 + u * 2) = __float2half_rn(v[2]);
            c1r[ci] = v[3];
        }
    __syncthreads();

    // ---- time loop ----
    for (int t = 0; t < T; ++t) {
        float d[4][4][4];
#pragma unroll
        for (int a = 0; a < 4; ++a)
#pragma unroll
            for (int b = 0; b < 4; ++b)
#pragma unroll
                for (int c = 0; c < 4; ++c) d[a][b][c] = 0.f;

        do_gemm(d, sm, O_H0, 0, w, lane);           // h0 @ Whh0^T
        if (t) do_gemm(d, sm, O_H1, 1, w, lane);    // h1 @ Wfold^T (prev folded)
        __syncthreads();                            // B1: all reads of h0 done

        float bs = (t > 0) ? 1.f : 0.f;
#pragma unroll
        for (int rt = 0; rt < 4; ++rt) {
            float hv[4];
#pragma unroll
            for (int j = 0; j < 4; ++j) {
                int row = rt * 16 + (lane >> 2) + ((j >> 1) << 3);
                int u   = w * 8 + ((lane & 3) << 1) + (j & 1);
                int s = shScen[row];
                const float* p0 = shP0 + s * 520;
                float ip = d[rt][0][j] + p0[u]       + bs * shBF[u];
                float fp = d[rt][1][j] + p0[128 + u] + bs * shBF[128 + u];
                float gp = d[rt][2][j] + p0[256 + u] + bs * shBF[256 + u];
                float op = d[rt][3][j] + p0[384 + u] + bs * shBF[384 + u];
                int ci = rt * 4 + j;
                float cn = sigf(fp) * c0r[ci] + sigf(ip) * tanhf_(gp);
                c0r[ci] = cn;
                hv[j] = sigf(op) * tanhf_(cn);
            }
            int row0 = rt * 16 + (lane >> 2);
            int ub = w * 8 + ((lane & 3) << 1);
            *(__half2*)(sm + O_H0 + row0 * 272 + ub * 2)       = __floats2half2_rn(hv[0], hv[1]);
            *(__half2*)(sm + O_H0 + (row0 + 8) * 272 + ub * 2) = __floats2half2_rn(hv[2], hv[3]);
        }
        __syncthreads();                            // B2: h0n visible

#pragma unroll
        for (int a = 0; a < 4; ++a)
#pragma unroll
            for (int b = 0; b < 4; ++b)
#pragma unroll
                for (int c = 0; c < 4; ++c) d[a][b][c] = 0.f;
        do_gemm(d, sm, O_H0, 2, w, lane);           // h0n @ Wih1^T
        do_gemm(d, sm, O_H1, 3, w, lane);           // h1  @ Whh1^T
        __syncthreads();                            // B3: all reads of h1 done

#pragma unroll
        for (int rt = 0; rt < 4; ++rt) {
            float hv[4];
#pragma unroll
            for (int j = 0; j < 4; ++j) {
                int u = w * 8 + ((lane & 3) << 1) + (j & 1);
                float ip = d[rt][0][j] + shPre1[u];
                float fp = d[rt][1][j] + shPre1[128 + u];
                float gp = d[rt][2][j] + shPre1[256 + u];
                float op = d[rt][3][j] + shPre1[384 + u];
                int ci = rt * 4 + j;
                float cn = sigf(fp) * c1r[ci] + sigf(ip) * tanhf_(gp);
                c1r[ci] = cn;
                hv[j] = sigf(op) * tanhf_(cn);
            }
            int row0 = rt * 16 + (lane >> 2);
            int ub = w * 8 + ((lane & 3) << 1);
            *(__half2*)(sm + O_H1 + row0 * 272 + ub * 2)       = __floats2half2_rn(hv[0], hv[1]);
            *(__half2*)(sm + O_H1 + (row0 + 8) * 272 + ub * 2) = __floats2half2_rn(hv[2], hv[3]);
            *(float2*)(sm + O_H1F + row0 * 528 + ub * 4)       = make_float2(hv[0], hv[1]);
            *(float2*)(sm + O_H1F + (row0 + 8) * 528 + ub * 4) = make_float2(hv[2], hv[3]);
        }
        __syncthreads();                            // B4: h1n (fp16+fp32) visible

        // output head from fp32 h1n
        for (int idx = tid; idx < MR * NVAR; idx += THREADS) {
            int m = idx / NVAR, v = idx - m * NVAR;
            const float* hr = (const float*)(sm + O_H1F) + m * 132;
            const float* wr = shWout + v * 128;
            float s0 = shBout[v], s1 = 0.f, s2 = 0.f, s3 = 0.f;
#pragma unroll 8
            for (int k = 0; k < 128; k += 4) {
                s0 = fmaf(hr[k],     wr[k],     s0);
                s1 = fmaf(hr[k + 1], wr[k + 1], s1);
                s2 = fmaf(hr[k + 2], wr[k + 2], s2);
                s3 = fmaf(hr[k + 3], wr[k + 3], s3);
            }
            outp[((size_t)(m0 + m) * T + t) * NVAR + v] = (s0 + s1) + (s2 + s3);
        }
        // next-step G0 reads h0/h1: stable since B2/B4; no extra barrier needed
    }
}

extern "C" void kernel_launch(void* const* d_in, const int* in_sizes, int n_in,
                              void* d_out, int out_size) {
    int off = (n_in >= 16) ? 1 : 0;
    const float* z      = (const float*)d_in[0];
    const int*   scen   = (const int*)d_in[1];
    const float* emb    = (const float*)d_in[2 + off];
    const float* W_init = (const float*)d_in[3 + off];
    const float* b_init = (const float*)d_in[4 + off];
    const float* W_ih0  = (const float*)d_in[5 + off];
    const float* W_hh0  = (const float*)d_in[6 + off];
    const float* b_ih0  = (const float*)d_in[7 + off];
    const float* b_hh0  = (const float*)d_in[8 + off];
    const float* W_ih1  = (const float*)d_in[9 + off];
    const float* W_hh1  = (const float*)d_in[10 + off];
    const float* b_ih1  = (const float*)d_in[11 + off];
    const float* b_hh1  = (const float*)d_in[12 + off];
    const float* W_out  = (const float*)d_in[13 + off];
    const float* b_out  = (const float*)d_in[14 + off];
    float* outp = (float*)d_out;

    int B = in_sizes[0] / 32;
    int T = out_size / (B * NVAR);

    int setup_n = 262144 + 5120;
    setup_kernel<<<(setup_n + 255) / 256, 256>>>(emb, W_init, b_init, W_ih0, b_ih0,
                                                 b_hh0, W_ih1, W_hh1, b_ih1, b_hh1,
                                                 W_hh0, W_out, b_out);
    cudaFuncSetAttribute(lstm_mma, cudaFuncAttributeMaxDynamicSharedMemorySize, SMEM_SZ);
    lstm_mma<<<B / MR, THREADS, SMEM_SZ>>>(z, scen, W_init, W_out, b_out, outp, T);
}